// round 2
// baseline (speedup 1.0000x reference)
#include <cuda_runtime.h>
#include <math.h>

#define LSEQ 2048
#define NB 4
#define NH 8
#define NE 64
#define LWS 6        // ceil(log2(2048)/2)
#define MAXNNZ 64    // max allowed cols per row = 47

// Per-row allowed-column lists (regenerated every launch; mask is a fixed
// function of L in the reference, so we port its builder exactly).
__device__ int g_cols[LSEQ * MAXNNZ];
__device__ int g_cnt[LSEQ];

// ---------------------------------------------------------------------------
// Kernel 1: procedural port of _build_local_log_symmetry_mask, emitting the
// sorted unique allowed-column list per row. One thread per row.
// ---------------------------------------------------------------------------
__global__ void build_lists_proc() {
    const int i = blockIdx.x * blockDim.x + threadIdx.x;
    if (i >= LSEQ) return;

    const int base = i * MAXNNZ;
    int cnt = 0;

    const int lstart = i - LWS + 1;  // left window start
    const int rend   = i + LWS - 1;  // right window end

    // Left log-spaced points: ni = lstart - int(1.5^k), collected descending,
    // emitted ascending. Only present when lstart >= 0 (reference branch).
    if (lstart >= 0) {
        int lefts[24];
        int nl = 0;
        double p = 1.0;
        int prev = -1;
        for (int k = 0; k < 128; k++) {
            const int off = (int)p;       // matches Python int(1.5**k) truncation
            const int ni = lstart - off;
            if (ni < 0) break;            // reference breaks at first OOB
            if (ni != prev) { lefts[nl++] = ni; prev = ni; }
            p *= 1.5;
        }
        for (int j = nl - 1; j >= 0; j--) g_cols[base + cnt++] = lefts[j];
    }

    // Contiguous window. Edge branches: lstart<0 -> row[:i]=1 plus right
    // window i..rend => 0..rend. rend>=L -> row[i:]=1 plus left window => lstart..L-1.
    const int lo = (lstart < 0) ? 0 : lstart;
    const int hi = (rend >= LSEQ) ? (LSEQ - 1) : rend;
    for (int c = lo; c <= hi; c++) g_cols[base + cnt++] = c;

    // Right log-spaced points: ni = rend + int(1.5^k), ascending.
    if (rend < LSEQ) {
        double p = 1.0;
        int prev = -1;
        for (int k = 0; k < 128; k++) {
            const int off = (int)p;
            const int ni = rend + off;
            if (ni >= LSEQ) break;
            if (ni != prev) { g_cols[base + cnt++] = ni; prev = ni; }
            p *= 1.5;
        }
    }
    g_cnt[i] = cnt;
}

// ---------------------------------------------------------------------------
// Kernel 2: sparse attention. Block = (query row i, batch b); warp = head h.
// Lane l owns candidate columns l and l+32.
// ---------------------------------------------------------------------------
__global__ __launch_bounds__(256) void attn(const float* __restrict__ q,
                                            const float* __restrict__ k,
                                            const float* __restrict__ v,
                                            float* __restrict__ out) {
    const int i = blockIdx.x;
    const int b = blockIdx.y;
    const int t = threadIdx.x;
    const int lane = t & 31;
    const int h = t >> 5;

    __shared__ float q_s[NH * NE];
    __shared__ int cols_s[MAXNNZ];
    __shared__ int ncols_s;

    // Load all 8 heads' Q for this (b,i): 512 contiguous floats.
    const float* qrow = q + (size_t)(b * LSEQ + i) * NH * NE;
    reinterpret_cast<float2*>(q_s)[t] = reinterpret_cast<const float2*>(qrow)[t];
    if (t < MAXNNZ) cols_s[t] = g_cols[i * MAXNNZ + t];
    if (t == 0) ncols_s = g_cnt[i];
    __syncthreads();

    const int n = ncols_s;
    const float* qh = q_s + h * NE;

    // ---- Phase 1: scores. Lane l computes s for columns cols[l], cols[l+32].
    float s0 = -INFINITY, s1 = -INFINITY;
    if (lane < n) {
        const int c = cols_s[lane];
        const float4* kr = reinterpret_cast<const float4*>(
            k + ((size_t)(b * LSEQ + c) * NH + h) * NE);
        float acc = 0.f;
#pragma unroll
        for (int x = 0; x < 16; x++) {
            float4 kk = kr[x];
            acc += kk.x * qh[4 * x + 0] + kk.y * qh[4 * x + 1] +
                   kk.z * qh[4 * x + 2] + kk.w * qh[4 * x + 3];
        }
        s0 = acc * 0.125f;  // 1/sqrt(64)
    }
    if (lane + 32 < n) {
        const int c = cols_s[lane + 32];
        const float4* kr = reinterpret_cast<const float4*>(
            k + ((size_t)(b * LSEQ + c) * NH + h) * NE);
        float acc = 0.f;
#pragma unroll
        for (int x = 0; x < 16; x++) {
            float4 kk = kr[x];
            acc += kk.x * qh[4 * x + 0] + kk.y * qh[4 * x + 1] +
                   kk.z * qh[4 * x + 2] + kk.w * qh[4 * x + 3];
        }
        s1 = acc * 0.125f;
    }

    // ---- Softmax over the <=64 scores held 2-per-lane.
    float m = fmaxf(s0, s1);
#pragma unroll
    for (int o = 16; o >= 1; o >>= 1) m = fmaxf(m, __shfl_xor_sync(0xffffffffu, m, o));

    float e0 = __expf(s0 - m);   // exp(-inf) -> 0 for invalid lanes
    float e1 = __expf(s1 - m);
    float sum = e0 + e1;
#pragma unroll
    for (int o = 16; o >= 1; o >>= 1) sum += __shfl_xor_sync(0xffffffffu, sum, o);

    const float inv = 1.0f / sum;
    const float p0 = e0 * inv;
    const float p1 = e1 * inv;

    // ---- Phase 2: output = sum_j p_j * V[col_j]. Coalesced: lane -> dim l, l+32.
    float acc0 = 0.f, acc1 = 0.f;
    for (int j = 0; j < n; j++) {
        const int c = cols_s[j];
        const float pj = __shfl_sync(0xffffffffu, (j < 32) ? p0 : p1, j & 31);
        const float* vr = v + ((size_t)(b * LSEQ + c) * NH + h) * NE;
        acc0 += pj * vr[lane];
        acc1 += pj * vr[lane + 32];
    }

    float* orow = out + ((size_t)(b * LSEQ + i) * NH + h) * NE;
    orow[lane] = acc0;
    orow[lane + 32] = acc1;
}

extern "C" void kernel_launch(void* const* d_in, const int* in_sizes, int n_in,
                              void* d_out, int out_size) {
    const float* q = (const float*)d_in[0];  // [B,L,H,E] f32
    const float* k = (const float*)d_in[1];  // [B,L,H,E] f32
    const float* v = (const float*)d_in[2];  // [B,L,H,D] f32

    build_lists_proc<<<8, 256>>>();
    dim3 grid(LSEQ, NB);
    attn<<<grid, 256>>>(q, k, v, (float*)d_out);
}

// round 3
// speedup vs baseline: 1.4904x; 1.4904x over previous
#include <cuda_runtime.h>
#include <math.h>

#define LSEQ 2048
#define NB 4
#define NH 8
#define NE 64
#define LWS 6        // ceil(log2(2048)/2)
#define MAXNNZ 64    // max allowed cols per row = 47
#define NCPAD 48     // padded column count (3 tiles of 16)
#define TCOLS 16     // columns per smem tile
#define KSTR 528     // smem row stride in floats (512 + 16 pad -> conflict-free)

// Per-row allowed-column lists (regenerated every launch; mask is a fixed
// function of L in the reference, so we port its builder exactly).
__device__ int g_cols[LSEQ * MAXNNZ];
__device__ int g_cnt[LSEQ];

// ---------------------------------------------------------------------------
// Kernel 1: procedural port of _build_local_log_symmetry_mask, emitting the
// sorted unique allowed-column list per row. One thread per row.
// ---------------------------------------------------------------------------
__global__ void build_lists_proc() {
    const int i = blockIdx.x * blockDim.x + threadIdx.x;
    if (i >= LSEQ) return;

    const int base = i * MAXNNZ;
    int cnt = 0;

    const int lstart = i - LWS + 1;  // left window start
    const int rend   = i + LWS - 1;  // right window end

    if (lstart >= 0) {
        int lefts[24];
        int nl = 0;
        double p = 1.0;
        int prev = -1;
        for (int k = 0; k < 128; k++) {
            const int off = (int)p;       // matches Python int(1.5**k)
            const int ni = lstart - off;
            if (ni < 0) break;
            if (ni != prev) { lefts[nl++] = ni; prev = ni; }
            p *= 1.5;
        }
        for (int j = nl - 1; j >= 0; j--) g_cols[base + cnt++] = lefts[j];
    }

    const int lo = (lstart < 0) ? 0 : lstart;
    const int hi = (rend >= LSEQ) ? (LSEQ - 1) : rend;
    for (int c = lo; c <= hi; c++) g_cols[base + cnt++] = c;

    if (rend < LSEQ) {
        double p = 1.0;
        int prev = -1;
        for (int k = 0; k < 128; k++) {
            const int off = (int)p;
            const int ni = rend + off;
            if (ni >= LSEQ) break;
            if (ni != prev) { g_cols[base + cnt++] = ni; prev = ni; }
            p *= 1.5;
        }
    }
    g_cnt[i] = cnt;
}

// ---------------------------------------------------------------------------
// Kernel 2: sparse attention with smem-staged K.
// Block = (query row i, batch b), 256 threads; warp = head h.
// ---------------------------------------------------------------------------
__global__ __launch_bounds__(256) void attn(const float* __restrict__ q,
                                            const float* __restrict__ k,
                                            const float* __restrict__ v,
                                            float* __restrict__ out) {
    const int i = blockIdx.x;
    const int b = blockIdx.y;
    const int t = threadIdx.x;
    const int lane = t & 31;
    const int wid = t >> 5;
    const int h = wid;

    __shared__ float k_s[TCOLS * KSTR];   // 16 staged K column-rows (all heads)
    __shared__ float q_s[NH * NE];        // Q for all heads at (b,i)
    __shared__ float sc_s[NH][MAXNNZ];    // per-head scores
    __shared__ int cols_s[NCPAD];
    __shared__ int ncols_s;

    // ---- init: Q, column list (padded with col 0), scores = -inf
    const float* qrow = q + (size_t)(b * LSEQ + i) * NH * NE;
    reinterpret_cast<float2*>(q_s)[t] = reinterpret_cast<const float2*>(qrow)[t];

    const int n = g_cnt[i];
    if (t < NCPAD) cols_s[t] = (t < n) ? g_cols[i * MAXNNZ + t] : 0;
    if (t == 0) ncols_s = n;
    reinterpret_cast<float*>(sc_s)[t] = -INFINITY;
    reinterpret_cast<float*>(sc_s)[t + 256] = -INFINITY;
    __syncthreads();

    const float4* q4 = reinterpret_cast<const float4*>(q_s);

    // ---- Phase 1: scores via smem-staged K, 3 tiles of 16 columns.
#pragma unroll 1
    for (int tile = 0; tile < NCPAD / TCOLS; tile++) {
        const int base = tile * TCOLS;

        // Load: warp wid stages local columns 2*wid and 2*wid+1 (coalesced 2KB rows).
#pragma unroll
        for (int cc = 0; cc < 2; cc++) {
            const int j = 2 * wid + cc;
            const int c = cols_s[base + j];
            const float4* src = reinterpret_cast<const float4*>(
                k + (size_t)(b * LSEQ + c) * NH * NE);
            float4* dst = reinterpret_cast<float4*>(k_s) + j * (KSTR / 4);
#pragma unroll
            for (int x = 0; x < 4; x++) dst[lane + 32 * x] = src[lane + 32 * x];
        }
        __syncthreads();

        // Compute: 4 lanes per column, each lane dots 16 dims of head h.
        const int lq = lane & 3;            // quarter within column group
#pragma unroll
        for (int p = 0; p < 2; p++) {
            const int jloc = p * 8 + (lane >> 2);
            const float4* kc = reinterpret_cast<const float4*>(k_s) + jloc * (KSTR / 4);
            float acc = 0.f;
#pragma unroll
            for (int x = 0; x < 4; x++) {
                const float4 kk = kc[h * 16 + lq + 4 * x];
                const float4 qq = q4[h * 16 + lq + 4 * x];
                acc += kk.x * qq.x + kk.y * qq.y + kk.z * qq.z + kk.w * qq.w;
            }
            acc += __shfl_xor_sync(0xffffffffu, acc, 1);
            acc += __shfl_xor_sync(0xffffffffu, acc, 2);
            const int jg = base + jloc;
            if (lq == 0 && jg < n) sc_s[h][jg] = acc * 0.125f;  // 1/sqrt(64)
        }
        __syncthreads();
    }

    // ---- Softmax over <=64 scores, 2 per lane.
    const float s0 = sc_s[h][lane];
    const float s1 = sc_s[h][lane + 32];
    float m = fmaxf(s0, s1);
#pragma unroll
    for (int o = 16; o >= 1; o >>= 1) m = fmaxf(m, __shfl_xor_sync(0xffffffffu, m, o));

    const float e0 = __expf(s0 - m);   // exp(-inf) -> 0 for invalid slots
    const float e1 = __expf(s1 - m);
    float sum = e0 + e1;
#pragma unroll
    for (int o = 16; o >= 1; o >>= 1) sum += __shfl_xor_sync(0xffffffffu, sum, o);

    const float inv = 1.0f / sum;
    const float p0 = e0 * inv;
    const float p1 = e1 * inv;

    // ---- Phase 2: out = sum_j p_j * V[col_j]. Lane -> dims 2*lane, 2*lane+1.
    float ax = 0.f, ay = 0.f;
    const int nn = ncols_s;
    for (int j = 0; j < nn; j++) {
        const int c = cols_s[j];
        const float pj = __shfl_sync(0xffffffffu, (j < 32) ? p0 : p1, j & 31);
        const float2 vv = reinterpret_cast<const float2*>(
            v + ((size_t)(b * LSEQ + c) * NH + h) * NE)[lane];
        ax += pj * vv.x;
        ay += pj * vv.y;
    }

    float2* orow = reinterpret_cast<float2*>(out + ((size_t)(b * LSEQ + i) * NH + h) * NE);
    float2 o2; o2.x = ax; o2.y = ay;
    orow[lane] = o2;
}

extern "C" void kernel_launch(void* const* d_in, const int* in_sizes, int n_in,
                              void* d_out, int out_size) {
    const float* q = (const float*)d_in[0];  // [B,L,H,E] f32
    const float* k = (const float*)d_in[1];  // [B,L,H,E] f32
    const float* v = (const float*)d_in[2];  // [B,L,H,D] f32

    build_lists_proc<<<8, 256>>>();
    dim3 grid(LSEQ, NB);
    attn<<<grid, 256>>>(q, k, v, (float*)d_out);
}

// round 4
// speedup vs baseline: 1.9448x; 1.3050x over previous
#include <cuda_runtime.h>
#include <math.h>

#define LSEQ 2048
#define NB 4
#define NH 8
#define NE 64
#define LWS 6        // ceil(log2(2048)/2)
#define MAXNNZ 64    // max allowed cols per row = 47
#define NCPAD 48     // padded column slots (6 per warp)

// Per-row allowed-column lists (regenerated every launch; mask is a fixed
// function of L in the reference, so we port its builder exactly).
__device__ int g_cols[LSEQ * MAXNNZ];
__device__ int g_cnt[LSEQ];

// ---------------------------------------------------------------------------
// Kernel 1: procedural port of _build_local_log_symmetry_mask, emitting the
// sorted unique allowed-column list per row. One thread per row.
// ---------------------------------------------------------------------------
__global__ void build_lists_proc() {
    const int i = blockIdx.x * blockDim.x + threadIdx.x;
    if (i >= LSEQ) return;

    const int base = i * MAXNNZ;
    int cnt = 0;

    const int lstart = i - LWS + 1;  // left window start
    const int rend   = i + LWS - 1;  // right window end

    if (lstart >= 0) {
        int lefts[24];
        int nl = 0;
        double p = 1.0;
        int prev = -1;
        for (int k = 0; k < 128; k++) {
            const int off = (int)p;       // matches Python int(1.5**k)
            const int ni = lstart - off;
            if (ni < 0) break;
            if (ni != prev) { lefts[nl++] = ni; prev = ni; }
            p *= 1.5;
        }
        for (int j = nl - 1; j >= 0; j--) g_cols[base + cnt++] = lefts[j];
    }

    const int lo = (lstart < 0) ? 0 : lstart;
    const int hi = (rend >= LSEQ) ? (LSEQ - 1) : rend;
    for (int c = lo; c <= hi; c++) g_cols[base + cnt++] = c;

    if (rend < LSEQ) {
        double p = 1.0;
        int prev = -1;
        for (int k = 0; k < 128; k++) {
            const int off = (int)p;
            const int ni = rend + off;
            if (ni >= LSEQ) break;
            if (ni != prev) { g_cols[base + cnt++] = ni; prev = ni; }
            p *= 1.5;
        }
    }
    g_cnt[i] = cnt;
}

// ---------------------------------------------------------------------------
// Kernel 2: sparse attention, register-resident K path.
// Block = (query row i, batch b), 256 threads; warp w owns columns w+8t.
// Element mapping: float4 index (lane+32x) of a 512-float row ->
//   head = (lane+32x)>>4, i.e. per x the warp covers heads 2x (lanes 0-15)
//   and 2x+1 (lanes 16-31).
// ---------------------------------------------------------------------------
__global__ __launch_bounds__(256) void attn(const float* __restrict__ q,
                                            const float* __restrict__ k,
                                            const float* __restrict__ v,
                                            float* __restrict__ out) {
    const int i = blockIdx.x;
    const int b = blockIdx.y;
    const int t = threadIdx.x;
    const int lane = t & 31;
    const int wid = t >> 5;
    const int h = wid;

    __shared__ float sc_s[NH][MAXNNZ];   // scores, then reused for probs
    __shared__ int cols_s[NCPAD];
    __shared__ int ncols_s;

    // ---- init: column list (padded with col 0), scores = -inf
    const int n = g_cnt[i];
    if (t < NCPAD) cols_s[t] = (t < n) ? g_cols[i * MAXNNZ + t] : 0;
    if (t == 0) ncols_s = n;
    reinterpret_cast<float*>(sc_s)[t] = -INFINITY;
    reinterpret_cast<float*>(sc_s)[t + 256] = -INFINITY;

    // ---- Q preload (registers, coalesced; L1-hit for warps 1..7)
    const float4* qp = reinterpret_cast<const float4*>(
        q + (size_t)(b * LSEQ + i) * (NH * NE));
    float4 qv[4];
#pragma unroll
    for (int x = 0; x < 4; x++) qv[x] = qp[lane + 32 * x];

    __syncthreads();

    // ---- Phase 1: scores straight from registers. 6 columns per warp.
#pragma unroll 3
    for (int tt = 0; tt < NCPAD / NH; tt++) {
        const int j = wid + NH * tt;
        const int c = cols_s[j];
        const float4* kp = reinterpret_cast<const float4*>(
            k + (size_t)(b * LSEQ + c) * (NH * NE));
        float a[4];
#pragma unroll
        for (int x = 0; x < 4; x++) {
            const float4 kv = kp[lane + 32 * x];
            a[x] = kv.x * qv[x].x + kv.y * qv[x].y + kv.z * qv[x].z + kv.w * qv[x].w;
        }
        // segmented sum over each 16-lane group
#pragma unroll
        for (int x = 0; x < 4; x++) {
            a[x] += __shfl_xor_sync(0xffffffffu, a[x], 1);
            a[x] += __shfl_xor_sync(0xffffffffu, a[x], 2);
            a[x] += __shfl_xor_sync(0xffffffffu, a[x], 4);
            a[x] += __shfl_xor_sync(0xffffffffu, a[x], 8);
        }
        if ((lane & 15) == 0 && j < n) {
            const int g = lane >> 4;
#pragma unroll
            for (int x = 0; x < 4; x++)
                sc_s[2 * x + g][j] = a[x] * 0.125f;   // 1/sqrt(64)
        }
    }
    __syncthreads();

    // ---- Softmax over <=64 scores, 2 per lane (warp h owns row h).
    const float s0 = sc_s[h][lane];
    const float s1 = sc_s[h][lane + 32];
    float m = fmaxf(s0, s1);
#pragma unroll
    for (int o = 16; o >= 1; o >>= 1) m = fmaxf(m, __shfl_xor_sync(0xffffffffu, m, o));

    const float e0 = __expf(s0 - m);   // exp(-inf) -> 0 for padded slots
    const float e1 = __expf(s1 - m);
    float sum = e0 + e1;
#pragma unroll
    for (int o = 16; o >= 1; o >>= 1) sum += __shfl_xor_sync(0xffffffffu, sum, o);

    const float inv = 1.0f / sum;
    // publish probabilities in this warp's score row (padded slots = 0)
    sc_s[h][lane] = e0 * inv;
    sc_s[h][lane + 32] = e1 * inv;
    __syncwarp();

    // ---- Phase 2: out = sum_j p_j * V[col_j]; 2 columns per iteration,
    //      half-warp per column, float4 per lane (dims 4*(lane&15)..+3).
    const int nn = ncols_s;
    const int half = lane >> 4;
    const int dq = lane & 15;
    float4 acc; acc.x = 0.f; acc.y = 0.f; acc.z = 0.f; acc.w = 0.f;
    for (int j = 0; j < nn; j += 2) {
        const int jj = j + half;            // <= 47 always (cols_s padded)
        const int c = cols_s[jj];
        const float pj = sc_s[h][jj];       // 0 for jj == nn (odd-n pad)
        const float4 vv = reinterpret_cast<const float4*>(
            v + ((size_t)(b * LSEQ + c) * NH + h) * NE)[dq];
        acc.x += pj * vv.x;
        acc.y += pj * vv.y;
        acc.z += pj * vv.z;
        acc.w += pj * vv.w;
    }
    // combine the two halves
    acc.x += __shfl_xor_sync(0xffffffffu, acc.x, 16);
    acc.y += __shfl_xor_sync(0xffffffffu, acc.y, 16);
    acc.z += __shfl_xor_sync(0xffffffffu, acc.z, 16);
    acc.w += __shfl_xor_sync(0xffffffffu, acc.w, 16);

    if (half == 0) {
        float4* orow = reinterpret_cast<float4*>(
            out + ((size_t)(b * LSEQ + i) * NH + h) * NE);
        orow[dq] = acc;
    }
}

extern "C" void kernel_launch(void* const* d_in, const int* in_sizes, int n_in,
                              void* d_out, int out_size) {
    const float* q = (const float*)d_in[0];  // [B,L,H,E] f32
    const float* k = (const float*)d_in[1];  // [B,L,H,E] f32
    const float* v = (const float*)d_in[2];  // [B,L,H,D] f32

    build_lists_proc<<<8, 256>>>();
    dim3 grid(LSEQ, NB);
    attn<<<grid, 256>>>(q, k, v, (float*)d_out);
}

// round 5
// speedup vs baseline: 2.1298x; 1.0951x over previous
#include <cuda_runtime.h>
#include <cuda_fp16.h>
#include <math.h>

#define LSEQ 2048
#define NB 4
#define NH 8
#define NE 64
#define LWS 6        // ceil(log2(2048)/2)
#define MAXNNZ 64    // max allowed cols per row = 47
#define NCPAD 48     // padded column slots (6 per warp)
#define NELEM (NB * LSEQ * NH * NE)   // 4,194,304

// Per-row allowed-column lists + fp16 copies of K and V (device scratch).
__device__ int g_cols[LSEQ * MAXNNZ];
__device__ int g_cnt[LSEQ];
__device__ __half gK16[NELEM];   // 8 MB
__device__ __half gV16[NELEM];   // 8 MB

// ---------------------------------------------------------------------------
// Kernel 0: convert K and V to fp16 (coalesced, 4 floats per thread each).
// ---------------------------------------------------------------------------
__global__ __launch_bounds__(256) void to_fp16(const float* __restrict__ k,
                                               const float* __restrict__ v) {
    const int idx = blockIdx.x * blockDim.x + threadIdx.x;   // float4 index
    {
        const float4 f = reinterpret_cast<const float4*>(k)[idx];
        __half2 h01 = __floats2half2_rn(f.x, f.y);
        __half2 h23 = __floats2half2_rn(f.z, f.w);
        uint2 st;
        st.x = *reinterpret_cast<unsigned int*>(&h01);
        st.y = *reinterpret_cast<unsigned int*>(&h23);
        reinterpret_cast<uint2*>(gK16)[idx] = st;
    }
    {
        const float4 f = reinterpret_cast<const float4*>(v)[idx];
        __half2 h01 = __floats2half2_rn(f.x, f.y);
        __half2 h23 = __floats2half2_rn(f.z, f.w);
        uint2 st;
        st.x = *reinterpret_cast<unsigned int*>(&h01);
        st.y = *reinterpret_cast<unsigned int*>(&h23);
        reinterpret_cast<uint2*>(gV16)[idx] = st;
    }
}

// ---------------------------------------------------------------------------
// Kernel 1: procedural port of _build_local_log_symmetry_mask.
// ---------------------------------------------------------------------------
__global__ void build_lists_proc() {
    const int i = blockIdx.x * blockDim.x + threadIdx.x;
    if (i >= LSEQ) return;

    const int base = i * MAXNNZ;
    int cnt = 0;

    const int lstart = i - LWS + 1;
    const int rend   = i + LWS - 1;

    if (lstart >= 0) {
        int lefts[24];
        int nl = 0;
        double p = 1.0;
        int prev = -1;
        for (int kk = 0; kk < 128; kk++) {
            const int off = (int)p;       // matches Python int(1.5**k)
            const int ni = lstart - off;
            if (ni < 0) break;
            if (ni != prev) { lefts[nl++] = ni; prev = ni; }
            p *= 1.5;
        }
        for (int j = nl - 1; j >= 0; j--) g_cols[base + cnt++] = lefts[j];
    }

    const int lo = (lstart < 0) ? 0 : lstart;
    const int hi = (rend >= LSEQ) ? (LSEQ - 1) : rend;
    for (int c = lo; c <= hi; c++) g_cols[base + cnt++] = c;

    if (rend < LSEQ) {
        double p = 1.0;
        int prev = -1;
        for (int kk = 0; kk < 128; kk++) {
            const int off = (int)p;
            const int ni = rend + off;
            if (ni >= LSEQ) break;
            if (ni != prev) { g_cols[base + cnt++] = ni; prev = ni; }
            p *= 1.5;
        }
    }
    g_cnt[i] = cnt;
}

// ---------------------------------------------------------------------------
// Kernel 2: sparse attention, fp16 K/V, fp32 accumulation.
// Block = (query row i, batch b), 256 threads.
// Phase 1: warp w computes columns w+8t from full fp16 K rows.
//   uint4 index (lane+32x) of a 512-half row -> lane covers 8 dims
//   [8*(lane&7) .. +7] of head (lane>>3)+4x, x in {0,1}.
// Phase 2: warp = head h; 1 column/iter; lane owns dims 2*lane, 2*lane+1.
// ---------------------------------------------------------------------------
__global__ __launch_bounds__(256) void attn(const float* __restrict__ q,
                                            float* __restrict__ out) {
    const int i = blockIdx.x;
    const int b = blockIdx.y;
    const int t = threadIdx.x;
    const int lane = t & 31;
    const int wid = t >> 5;
    const int h = wid;

    __shared__ float sc_s[NH][MAXNNZ];   // scores
    __shared__ int cols_s[NCPAD];
    __shared__ int ncols_s;

    // ---- init: column list (padded with col 0), scores = -inf
    const int n = g_cnt[i];
    if (t < NCPAD) cols_s[t] = (t < n) ? g_cols[i * MAXNNZ + t] : 0;
    if (t == 0) ncols_s = n;
    reinterpret_cast<float*>(sc_s)[t] = -INFINITY;
    reinterpret_cast<float*>(sc_s)[t + 256] = -INFINITY;

    // ---- Q preload: q[head (lane>>3)+4x][dims 8*(lane&7)..+7], x in {0,1}
    const float4* qp = reinterpret_cast<const float4*>(
        q + (size_t)(b * LSEQ + i) * (NH * NE));
    float4 qv[2][2];
#pragma unroll
    for (int x = 0; x < 2; x++) {
        const int hh = (lane >> 3) + 4 * x;
        const int f4 = 16 * hh + 2 * (lane & 7);
        qv[x][0] = qp[f4];
        qv[x][1] = qp[f4 + 1];
    }

    __syncthreads();

    // ---- Phase 1: scores from fp16 K rows. 6 columns per warp.
#pragma unroll 3
    for (int tt = 0; tt < NCPAD / NH; tt++) {
        const int j = wid + NH * tt;
        const int c = cols_s[j];
        const uint4* kp = reinterpret_cast<const uint4*>(
            gK16 + (size_t)(b * LSEQ + c) * (NH * NE));
        float a[2];
#pragma unroll
        for (int x = 0; x < 2; x++) {
            const uint4 kk = kp[lane + 32 * x];
            const float2 k0 = __half22float2(*reinterpret_cast<const __half2*>(&kk.x));
            const float2 k1 = __half22float2(*reinterpret_cast<const __half2*>(&kk.y));
            const float2 k2 = __half22float2(*reinterpret_cast<const __half2*>(&kk.z));
            const float2 k3 = __half22float2(*reinterpret_cast<const __half2*>(&kk.w));
            a[x] = k0.x * qv[x][0].x + k0.y * qv[x][0].y +
                   k1.x * qv[x][0].z + k1.y * qv[x][0].w +
                   k2.x * qv[x][1].x + k2.y * qv[x][1].y +
                   k3.x * qv[x][1].z + k3.y * qv[x][1].w;
        }
        // segmented sum over each 8-lane group
#pragma unroll
        for (int x = 0; x < 2; x++) {
            a[x] += __shfl_xor_sync(0xffffffffu, a[x], 1);
            a[x] += __shfl_xor_sync(0xffffffffu, a[x], 2);
            a[x] += __shfl_xor_sync(0xffffffffu, a[x], 4);
        }
        if ((lane & 7) == 0 && j < n) {
            const int g = lane >> 3;
#pragma unroll
            for (int x = 0; x < 2; x++)
                sc_s[g + 4 * x][j] = a[x] * 0.125f;   // 1/sqrt(64)
        }
    }
    __syncthreads();

    // ---- Softmax over <=64 scores, 2 per lane (warp h owns row h).
    const float s0 = sc_s[h][lane];
    const float s1 = sc_s[h][lane + 32];
    float m = fmaxf(s0, s1);
#pragma unroll
    for (int o = 16; o >= 1; o >>= 1) m = fmaxf(m, __shfl_xor_sync(0xffffffffu, m, o));

    const float e0 = __expf(s0 - m);   // exp(-inf) -> 0 for padded slots
    const float e1 = __expf(s1 - m);
    float sum = e0 + e1;
#pragma unroll
    for (int o = 16; o >= 1; o >>= 1) sum += __shfl_xor_sync(0xffffffffu, sum, o);

    const float inv = 1.0f / sum;
    const float p0 = e0 * inv;
    const float p1 = e1 * inv;

    // ---- Phase 2: out = sum_j p_j * V16[col_j][h]; lane -> dims 2l, 2l+1.
    const int nn = ncols_s;
    float ax = 0.f, ay = 0.f;
    for (int j = 0; j < nn; j++) {
        const int c = cols_s[j];
        const float pj = __shfl_sync(0xffffffffu, (j < 32) ? p0 : p1, j & 31);
        const __half2 vv = reinterpret_cast<const __half2*>(
            gV16 + ((size_t)(b * LSEQ + c) * NH + h) * NE)[lane];
        const float2 f = __half22float2(vv);
        ax += pj * f.x;
        ay += pj * f.y;
    }

    float2 o2; o2.x = ax; o2.y = ay;
    reinterpret_cast<float2*>(out + ((size_t)(b * LSEQ + i) * NH + h) * NE)[lane] = o2;
}

extern "C" void kernel_launch(void* const* d_in, const int* in_sizes, int n_in,
                              void* d_out, int out_size) {
    const float* q = (const float*)d_in[0];  // [B,L,H,E] f32
    const float* k = (const float*)d_in[1];  // [B,L,H,E] f32
    const float* v = (const float*)d_in[2];  // [B,L,H,D] f32

    to_fp16<<<NELEM / 4 / 256, 256>>>(k, v);
    build_lists_proc<<<8, 256>>>();
    dim3 grid(LSEQ, NB);
    attn<<<grid, 256>>>(q, (float*)d_out);
}

// round 6
// speedup vs baseline: 2.3172x; 1.0880x over previous
#include <cuda_runtime.h>
#include <cuda_fp16.h>
#include <math.h>

#define LSEQ 2048
#define NB 4
#define NH 8
#define NE 64
#define LWS 6        // ceil(log2(2048)/2)
#define MAXNNZ 64    // max allowed cols per row = 47
#define NCPAD 48     // padded column slots (6 per warp)
#define NELEM (NB * LSEQ * NH * NE)   // 4,194,304

// Per-row allowed-column lists + fp16 copies of K and V (device scratch).
__device__ int g_cols[LSEQ * MAXNNZ];
__device__ int g_cnt[LSEQ];
__device__ __half gK16[NELEM];   // 8 MB
__device__ __half gV16[NELEM];   // 8 MB

// ---------------------------------------------------------------------------
// Kernel 0: convert K and V to fp16. One float4 per thread; K and V are
// handled by disjoint blocks (more parallelism for a latency-bound kernel).
// ---------------------------------------------------------------------------
__global__ __launch_bounds__(256) void to_fp16(const float* __restrict__ k,
                                               const float* __restrict__ v) {
    const unsigned gid = blockIdx.x * blockDim.x + threadIdx.x;  // 0 .. 2*NELEM/4-1
    const bool isV = gid >= (NELEM / 4);
    const unsigned idx = isV ? gid - (NELEM / 4) : gid;          // float4 index
    const float4 f = reinterpret_cast<const float4*>(isV ? v : k)[idx];
    __half2 h01 = __floats2half2_rn(f.x, f.y);
    __half2 h23 = __floats2half2_rn(f.z, f.w);
    uint2 st;
    st.x = *reinterpret_cast<unsigned int*>(&h01);
    st.y = *reinterpret_cast<unsigned int*>(&h23);
    reinterpret_cast<uint2*>(isV ? gV16 : gK16)[idx] = st;
}

// ---------------------------------------------------------------------------
// Kernel 1: procedural port of _build_local_log_symmetry_mask.
// ---------------------------------------------------------------------------
__global__ void build_lists_proc() {
    const int i = blockIdx.x * blockDim.x + threadIdx.x;
    if (i >= LSEQ) return;

    const int base = i * MAXNNZ;
    int cnt = 0;

    const int lstart = i - LWS + 1;
    const int rend   = i + LWS - 1;

    if (lstart >= 0) {
        int lefts[24];
        int nl = 0;
        double p = 1.0;
        int prev = -1;
        for (int kk = 0; kk < 128; kk++) {
            const int off = (int)p;       // matches Python int(1.5**k)
            const int ni = lstart - off;
            if (ni < 0) break;
            if (ni != prev) { lefts[nl++] = ni; prev = ni; }
            p *= 1.5;
        }
        for (int j = nl - 1; j >= 0; j--) g_cols[base + cnt++] = lefts[j];
    }

    const int lo = (lstart < 0) ? 0 : lstart;
    const int hi = (rend >= LSEQ) ? (LSEQ - 1) : rend;
    for (int c = lo; c <= hi; c++) g_cols[base + cnt++] = c;

    if (rend < LSEQ) {
        double p = 1.0;
        int prev = -1;
        for (int kk = 0; kk < 128; kk++) {
            const int off = (int)p;
            const int ni = rend + off;
            if (ni >= LSEQ) break;
            if (ni != prev) { g_cols[base + cnt++] = ni; prev = ni; }
            p *= 1.5;
        }
    }
    g_cnt[i] = cnt;
}

// ---------------------------------------------------------------------------
// Kernel 2: sparse attention, fp16 K/V, fp32 accumulation.
// Block = (query row i, batch b), 256 threads.
// Phase 1: warp w computes columns w+8t from full fp16 K rows.
// Phase 2: warp = head h; STATIC 48-iteration loop, probs from smem
//   (padded slots have p == 0), fully unrolled for MLP.
// ---------------------------------------------------------------------------
__global__ __launch_bounds__(256) void attn(const float* __restrict__ q,
                                            float* __restrict__ out) {
    const int i = blockIdx.x;
    const int b = blockIdx.y;
    const int t = threadIdx.x;
    const int lane = t & 31;
    const int wid = t >> 5;
    const int h = wid;

    __shared__ float sc_s[NH][MAXNNZ];   // scores, then probabilities
    __shared__ int cols_s[NCPAD];

    // ---- init: column list (padded with col 0), scores = -inf
    const int n = g_cnt[i];
    if (t < NCPAD) cols_s[t] = (t < n) ? g_cols[i * MAXNNZ + t] : 0;
    reinterpret_cast<float*>(sc_s)[t] = -INFINITY;
    reinterpret_cast<float*>(sc_s)[t + 256] = -INFINITY;

    // ---- Q preload: head (lane>>3)+4x, dims 8*(lane&7)..+7, x in {0,1}
    const float4* qp = reinterpret_cast<const float4*>(
        q + (size_t)(b * LSEQ + i) * (NH * NE));
    float4 qv[2][2];
#pragma unroll
    for (int x = 0; x < 2; x++) {
        const int hh = (lane >> 3) + 4 * x;
        const int f4 = 16 * hh + 2 * (lane & 7);
        qv[x][0] = qp[f4];
        qv[x][1] = qp[f4 + 1];
    }

    __syncthreads();

    // ---- Phase 1: scores from fp16 K rows. 6 columns per warp.
#pragma unroll
    for (int tt = 0; tt < NCPAD / NH; tt++) {
        const int j = wid + NH * tt;
        const int c = cols_s[j];
        const uint4* kp = reinterpret_cast<const uint4*>(
            gK16 + (size_t)(b * LSEQ + c) * (NH * NE));
        float a[2];
#pragma unroll
        for (int x = 0; x < 2; x++) {
            const uint4 kk = kp[lane + 32 * x];
            const float2 k0 = __half22float2(*reinterpret_cast<const __half2*>(&kk.x));
            const float2 k1 = __half22float2(*reinterpret_cast<const __half2*>(&kk.y));
            const float2 k2 = __half22float2(*reinterpret_cast<const __half2*>(&kk.z));
            const float2 k3 = __half22float2(*reinterpret_cast<const __half2*>(&kk.w));
            a[x] = k0.x * qv[x][0].x + k0.y * qv[x][0].y +
                   k1.x * qv[x][0].z + k1.y * qv[x][0].w +
                   k2.x * qv[x][1].x + k2.y * qv[x][1].y +
                   k3.x * qv[x][1].z + k3.y * qv[x][1].w;
        }
#pragma unroll
        for (int x = 0; x < 2; x++) {
            a[x] += __shfl_xor_sync(0xffffffffu, a[x], 1);
            a[x] += __shfl_xor_sync(0xffffffffu, a[x], 2);
            a[x] += __shfl_xor_sync(0xffffffffu, a[x], 4);
        }
        if ((lane & 7) == 0 && j < n) {
            const int g = lane >> 3;
#pragma unroll
            for (int x = 0; x < 2; x++)
                sc_s[g + 4 * x][j] = a[x] * 0.125f;   // 1/sqrt(64)
        }
    }
    __syncthreads();

    // ---- Softmax over <=64 scores, 2 per lane (warp h owns row h).
    const float s0 = sc_s[h][lane];
    const float s1 = sc_s[h][lane + 32];
    float m = fmaxf(s0, s1);
#pragma unroll
    for (int o = 16; o >= 1; o >>= 1) m = fmaxf(m, __shfl_xor_sync(0xffffffffu, m, o));

    const float e0 = __expf(s0 - m);   // exp(-inf) -> 0 for padded slots
    const float e1 = __expf(s1 - m);
    float sum = e0 + e1;
#pragma unroll
    for (int o = 16; o >= 1; o >>= 1) sum += __shfl_xor_sync(0xffffffffu, sum, o);

    const float inv = 1.0f / sum;
    // publish probabilities (padded slots become exactly 0)
    sc_s[h][lane] = e0 * inv;
    sc_s[h][lane + 32] = e1 * inv;
    __syncwarp();

    // ---- Phase 2: out = sum_j p_j * V16[col_j][h]. Static 48-iter loop,
    //      fully unrolled -> all LDGs independent and front-batched.
    const __half* vb = gV16 + ((size_t)b * LSEQ * NH + h) * NE;
    float ax = 0.f, ay = 0.f;
#pragma unroll
    for (int j = 0; j < NCPAD; j++) {
        const int c = cols_s[j];
        const float pj = sc_s[h][j];        // 0 for padded/odd slots
        const __half2 vv = reinterpret_cast<const __half2*>(
            vb + (size_t)c * (NH * NE))[lane];
        const float2 f = __half22float2(vv);
        ax += pj * f.x;
        ay += pj * f.y;
    }

    float2 o2; o2.x = ax; o2.y = ay;
    reinterpret_cast<float2*>(out + ((size_t)(b * LSEQ + i) * NH + h) * NE)[lane] = o2;
}

extern "C" void kernel_launch(void* const* d_in, const int* in_sizes, int n_in,
                              void* d_out, int out_size) {
    const float* q = (const float*)d_in[0];  // [B,L,H,E] f32
    const float* k = (const float*)d_in[1];  // [B,L,H,E] f32
    const float* v = (const float*)d_in[2];  // [B,L,H,D] f32

    to_fp16<<<2 * (NELEM / 4) / 256, 256>>>(k, v);
    build_lists_proc<<<8, 256>>>();
    dim3 grid(LSEQ, NB);
    attn<<<grid, 256>>>(q, (float*)d_out);
}

// round 7
// speedup vs baseline: 2.4397x; 1.0529x over previous
#include <cuda_runtime.h>
#include <cuda_fp16.h>
#include <math.h>

#define LSEQ 2048
#define NB 4
#define NH 8
#define NE 64
#define LWS 6        // ceil(log2(2048)/2)
#define MAXNNZ 64    // max allowed cols per row = 47
#define NCPAD 48     // padded column slots (6 per warp)
#define NELEM (NB * LSEQ * NH * NE)   // 4,194,304
#define NCVT (2 * (NELEM / 4) / 256)  // 8192 conversion blocks

// Per-row allowed-column lists + fp16 copies of K and V (device scratch).
__device__ int g_cols[LSEQ * MAXNNZ];
__device__ int g_cnt[LSEQ];
__device__ __half gK16[NELEM];   // 8 MB
__device__ __half gV16[NELEM];   // 8 MB

// ---------------------------------------------------------------------------
// Kernel 0 (fused): blocks [0, NCVT) convert K/V to fp16 (one float4/thread);
// blocks [NCVT, NCVT+8) run the procedural mask-list builder (1 thread/row).
// ---------------------------------------------------------------------------
__global__ __launch_bounds__(256) void prep(const float* __restrict__ k,
                                            const float* __restrict__ v) {
    if (blockIdx.x < NCVT) {
        const unsigned gid = blockIdx.x * blockDim.x + threadIdx.x;
        const bool isV = gid >= (NELEM / 4);
        const unsigned idx = isV ? gid - (NELEM / 4) : gid;   // float4 index
        const float4 f = reinterpret_cast<const float4*>(isV ? v : k)[idx];
        __half2 h01 = __floats2half2_rn(f.x, f.y);
        __half2 h23 = __floats2half2_rn(f.z, f.w);
        uint2 st;
        st.x = *reinterpret_cast<unsigned int*>(&h01);
        st.y = *reinterpret_cast<unsigned int*>(&h23);
        reinterpret_cast<uint2*>(isV ? gV16 : gK16)[idx] = st;
        return;
    }

    // ---- mask-list builder (exact port of _build_local_log_symmetry_mask)
    const int i = (blockIdx.x - NCVT) * blockDim.x + threadIdx.x;
    if (i >= LSEQ) return;

    const int base = i * MAXNNZ;
    int cnt = 0;

    const int lstart = i - LWS + 1;
    const int rend   = i + LWS - 1;

    if (lstart >= 0) {
        int lefts[24];
        int nl = 0;
        double p = 1.0;
        int prev = -1;
        for (int kk = 0; kk < 128; kk++) {
            const int off = (int)p;       // matches Python int(1.5**k)
            const int ni = lstart - off;
            if (ni < 0) break;
            if (ni != prev) { lefts[nl++] = ni; prev = ni; }
            p *= 1.5;
        }
        for (int j = nl - 1; j >= 0; j--) g_cols[base + cnt++] = lefts[j];
    }

    const int lo = (lstart < 0) ? 0 : lstart;
    const int hi = (rend >= LSEQ) ? (LSEQ - 1) : rend;
    for (int c = lo; c <= hi; c++) g_cols[base + cnt++] = c;

    if (rend < LSEQ) {
        double p = 1.0;
        int prev = -1;
        for (int kk = 0; kk < 128; kk++) {
            const int off = (int)p;
            const int ni = rend + off;
            if (ni >= LSEQ) break;
            if (ni != prev) { g_cols[base + cnt++] = ni; prev = ni; }
            p *= 1.5;
        }
    }
    g_cnt[i] = cnt;
}

// ---------------------------------------------------------------------------
// Kernel 1: sparse attention, fp16 K/V, fp32 accumulation.
// Block = (query row i, batch b), 256 threads; warp = head in phases 2/3.
// ---------------------------------------------------------------------------
__global__ __launch_bounds__(256) void attn(const float* __restrict__ q,
                                            float* __restrict__ out) {
    const int i = blockIdx.x;
    const int b = blockIdx.y;
    const int t = threadIdx.x;
    const int lane = t & 31;
    const int wid = t >> 5;
    const int h = wid;

    __shared__ float sc_s[NH][MAXNNZ];    // scores
    __shared__ float2 pp_s[NH][NCPAD];    // packed (col-bits, prob) pairs
    __shared__ int cols_s[NCPAD];

    // ---- init: column list (padded with col 0), scores = -inf
    const int n = g_cnt[i];
    if (t < NCPAD) cols_s[t] = (t < n) ? g_cols[i * MAXNNZ + t] : 0;
    reinterpret_cast<float*>(sc_s)[t] = -INFINITY;
    reinterpret_cast<float*>(sc_s)[t + 256] = -INFINITY;

    // ---- Q preload: head (lane>>3)+4x, dims 8*(lane&7)..+7, x in {0,1}
    const float4* qp = reinterpret_cast<const float4*>(
        q + (size_t)(b * LSEQ + i) * (NH * NE));
    float4 qv[2][2];
#pragma unroll
    for (int x = 0; x < 2; x++) {
        const int hh = (lane >> 3) + 4 * x;
        const int f4 = 16 * hh + 2 * (lane & 7);
        qv[x][0] = qp[f4];
        qv[x][1] = qp[f4 + 1];
    }

    __syncthreads();

    // ---- Phase 1: scores from fp16 K rows. 6 columns per warp.
#pragma unroll
    for (int tt = 0; tt < NCPAD / NH; tt++) {
        const int j = wid + NH * tt;
        const int c = cols_s[j];
        const uint4* kp = reinterpret_cast<const uint4*>(
            gK16 + (size_t)(b * LSEQ + c) * (NH * NE));
        float a[2];
#pragma unroll
        for (int x = 0; x < 2; x++) {
            const uint4 kk = kp[lane + 32 * x];
            const float2 k0 = __half22float2(*reinterpret_cast<const __half2*>(&kk.x));
            const float2 k1 = __half22float2(*reinterpret_cast<const __half2*>(&kk.y));
            const float2 k2 = __half22float2(*reinterpret_cast<const __half2*>(&kk.z));
            const float2 k3 = __half22float2(*reinterpret_cast<const __half2*>(&kk.w));
            a[x] = k0.x * qv[x][0].x + k0.y * qv[x][0].y +
                   k1.x * qv[x][0].z + k1.y * qv[x][0].w +
                   k2.x * qv[x][1].x + k2.y * qv[x][1].y +
                   k3.x * qv[x][1].z + k3.y * qv[x][1].w;
        }
#pragma unroll
        for (int x = 0; x < 2; x++) {
            a[x] += __shfl_xor_sync(0xffffffffu, a[x], 1);
            a[x] += __shfl_xor_sync(0xffffffffu, a[x], 2);
            a[x] += __shfl_xor_sync(0xffffffffu, a[x], 4);
        }
        if ((lane & 7) == 0 && j < n) {
            const int g = lane >> 3;
#pragma unroll
            for (int x = 0; x < 2; x++)
                sc_s[g + 4 * x][j] = a[x] * 0.125f;   // 1/sqrt(64)
        }
    }
    __syncthreads();

    // ---- Softmax over <=64 scores, 2 per lane (warp h owns row h).
    const float s0 = sc_s[h][lane];
    const float s1 = sc_s[h][lane + 32];
    float m = fmaxf(s0, s1);
#pragma unroll
    for (int o = 16; o >= 1; o >>= 1) m = fmaxf(m, __shfl_xor_sync(0xffffffffu, m, o));

    const float e0 = __expf(s0 - m);   // exp(-inf) -> 0 for padded slots
    const float e1 = __expf(s1 - m);
    float sum = e0 + e1;
#pragma unroll
    for (int o = 16; o >= 1; o >>= 1) sum += __shfl_xor_sync(0xffffffffu, sum, o);

    const float inv = __fdividef(1.0f, sum);
    // publish packed (col, prob) pairs; padded slots get prob == 0 exactly
    {
        float2 pr;
        pr.x = __int_as_float(cols_s[lane]);
        pr.y = e0 * inv;
        pp_s[h][lane] = pr;
        if (lane < NCPAD - 32) {
            float2 pr2;
            pr2.x = __int_as_float(cols_s[lane + 32]);
            pr2.y = e1 * inv;
            pp_s[h][lane + 32] = pr2;
        }
    }
    __syncwarp();

    // ---- Phase 2: out = sum_j p_j * V16[col_j][h]. 2 pairs per LDS.128,
    //      static fully-unrolled loop, two accumulator chains.
    const __half* vb = gV16 + ((size_t)b * LSEQ * NH + h) * NE;
    float ax = 0.f, ay = 0.f, bx = 0.f, by = 0.f;
    const float4* pp4 = reinterpret_cast<const float4*>(pp_s[h]);
#pragma unroll
    for (int j2 = 0; j2 < NCPAD / 2; j2++) {
        const float4 cp = pp4[j2];          // (col0, p0, col1, p1)
        const int c0 = __float_as_int(cp.x);
        const int c1 = __float_as_int(cp.z);
        const __half2 v0 = reinterpret_cast<const __half2*>(
            vb + (size_t)c0 * (NH * NE))[lane];
        const __half2 v1 = reinterpret_cast<const __half2*>(
            vb + (size_t)c1 * (NH * NE))[lane];
        const float2 f0 = __half22float2(v0);
        const float2 f1 = __half22float2(v1);
        ax += cp.y * f0.x;
        ay += cp.y * f0.y;
        bx += cp.w * f1.x;
        by += cp.w * f1.y;
    }

    float2 o2; o2.x = ax + bx; o2.y = ay + by;
    reinterpret_cast<float2*>(out + ((size_t)(b * LSEQ + i) * NH + h) * NE)[lane] = o2;
}

extern "C" void kernel_launch(void* const* d_in, const int* in_sizes, int n_in,
                              void* d_out, int out_size) {
    const float* q = (const float*)d_in[0];  // [B,L,H,E] f32
    const float* k = (const float*)d_in[1];  // [B,L,H,E] f32
    const float* v = (const float*)d_in[2];  // [B,L,H,D] f32

    prep<<<NCVT + 8, 256>>>(k, v);
    dim3 grid(LSEQ, NB);
    attn<<<grid, 256>>>(q, (float*)d_out);
}

// round 8
// speedup vs baseline: 2.5425x; 1.0422x over previous
#include <cuda_runtime.h>
#include <cuda_fp16.h>
#include <math.h>

#define LSEQ 2048
#define NB 4
#define NH 8
#define NE 64
#define LWS 6        // ceil(log2(2048)/2)
#define MAXNNZ 64    // max allowed cols per row = 47
#define NCPAD 48     // padded column slots (6 per warp)
#define NELEM (NB * LSEQ * NH * NE)   // 4,194,304
// conversion: each thread converts 2 float4s; K and V by disjoint blocks
#define NCVT (2 * (NELEM / 8) / 256)  // 4096 conversion blocks

// Per-row allowed-column lists + fp16 copies of K and V (device scratch).
__device__ int g_cols[LSEQ * MAXNNZ];
__device__ int g_cnt[LSEQ];
__device__ __half gK16[NELEM];   // 8 MB
__device__ __half gV16[NELEM];   // 8 MB

// ---------------------------------------------------------------------------
// Kernel 0 (fused): blocks [0, NCVT) convert K/V to fp16, 2 independent
// float4s per thread (MLP=2); blocks [NCVT, NCVT+8) build the mask lists.
// ---------------------------------------------------------------------------
__global__ __launch_bounds__(256) void prep(const float* __restrict__ k,
                                            const float* __restrict__ v) {
    if (blockIdx.x < NCVT) {
        const unsigned gid = blockIdx.x * blockDim.x + threadIdx.x;
        const bool isV = gid >= (NELEM / 8);
        const unsigned base = (isV ? gid - (NELEM / 8) : gid) * 2;  // float4 idx
        const float4* src = reinterpret_cast<const float4*>(isV ? v : k);
        uint2* dst = reinterpret_cast<uint2*>(isV ? gV16 : gK16);
        const float4 f0 = src[base];
        const float4 f1 = src[base + 1];
        uint2 s0, s1;
        {
            __half2 a = __floats2half2_rn(f0.x, f0.y);
            __half2 b = __floats2half2_rn(f0.z, f0.w);
            s0.x = *reinterpret_cast<unsigned int*>(&a);
            s0.y = *reinterpret_cast<unsigned int*>(&b);
        }
        {
            __half2 a = __floats2half2_rn(f1.x, f1.y);
            __half2 b = __floats2half2_rn(f1.z, f1.w);
            s1.x = *reinterpret_cast<unsigned int*>(&a);
            s1.y = *reinterpret_cast<unsigned int*>(&b);
        }
        dst[base] = s0;
        dst[base + 1] = s1;
        return;
    }

    // ---- mask-list builder (exact port of _build_local_log_symmetry_mask)
    const int i = (blockIdx.x - NCVT) * blockDim.x + threadIdx.x;
    if (i >= LSEQ) return;

    const int base = i * MAXNNZ;
    int cnt = 0;

    const int lstart = i - LWS + 1;
    const int rend   = i + LWS - 1;

    if (lstart >= 0) {
        int lefts[24];
        int nl = 0;
        double p = 1.0;
        int prev = -1;
        for (int kk = 0; kk < 128; kk++) {
            const int off = (int)p;       // matches Python int(1.5**k)
            const int ni = lstart - off;
            if (ni < 0) break;
            if (ni != prev) { lefts[nl++] = ni; prev = ni; }
            p *= 1.5;
        }
        for (int j = nl - 1; j >= 0; j--) g_cols[base + cnt++] = lefts[j];
    }

    const int lo = (lstart < 0) ? 0 : lstart;
    const int hi = (rend >= LSEQ) ? (LSEQ - 1) : rend;
    for (int c = lo; c <= hi; c++) g_cols[base + cnt++] = c;

    if (rend < LSEQ) {
        double p = 1.0;
        int prev = -1;
        for (int kk = 0; kk < 128; kk++) {
            const int off = (int)p;
            const int ni = rend + off;
            if (ni >= LSEQ) break;
            if (ni != prev) { g_cols[base + cnt++] = ni; prev = ni; }
            p *= 1.5;
        }
    }
    g_cnt[i] = cnt;
}

// ---------------------------------------------------------------------------
// Kernel 1: sparse attention, fp16 K/V, fp32 accumulation.
// Block = (query row i, batch b), 256 threads; 6 CTAs/SM target.
// ---------------------------------------------------------------------------
__global__ __launch_bounds__(256, 6) void attn(const float* __restrict__ q,
                                               float* __restrict__ out) {
    const int i = blockIdx.x;
    const int b = blockIdx.y;
    const int t = threadIdx.x;
    const int lane = t & 31;
    const int wid = t >> 5;
    const int h = wid;

    __shared__ float sc_s[NH][MAXNNZ];    // scores
    __shared__ float2 pp_s[NH][NCPAD];    // packed (col-bits, prob) pairs
    __shared__ int cols_s[NCPAD];

    // ---- init: column list (padded with col 0), scores = -inf
    const int n = g_cnt[i];
    if (t < NCPAD) cols_s[t] = (t < n) ? g_cols[i * MAXNNZ + t] : 0;
    reinterpret_cast<float*>(sc_s)[t] = -INFINITY;
    reinterpret_cast<float*>(sc_s)[t + 256] = -INFINITY;

    // ---- Q preload, pre-scaled by 1/sqrt(64):
    //      head (lane>>3)+4x, dims 8*(lane&7)..+7, x in {0,1}
    const float4* qp = reinterpret_cast<const float4*>(
        q + (size_t)(b * LSEQ + i) * (NH * NE));
    float4 qv[2][2];
#pragma unroll
    for (int x = 0; x < 2; x++) {
        const int hh = (lane >> 3) + 4 * x;
        const int f4 = 16 * hh + 2 * (lane & 7);
        qv[x][0] = qp[f4];
        qv[x][1] = qp[f4 + 1];
        qv[x][0].x *= 0.125f; qv[x][0].y *= 0.125f;
        qv[x][0].z *= 0.125f; qv[x][0].w *= 0.125f;
        qv[x][1].x *= 0.125f; qv[x][1].y *= 0.125f;
        qv[x][1].z *= 0.125f; qv[x][1].w *= 0.125f;
    }

    __syncthreads();

    // ---- Phase 1: scores from fp16 K rows. 6 columns per warp.
#pragma unroll
    for (int tt = 0; tt < NCPAD / NH; tt++) {
        const int j = wid + NH * tt;
        const int c = cols_s[j];
        const uint4* kp = reinterpret_cast<const uint4*>(
            gK16 + (size_t)(b * LSEQ + c) * (NH * NE));
        float a[2];
#pragma unroll
        for (int x = 0; x < 2; x++) {
            const uint4 kk = kp[lane + 32 * x];
            const float2 k0 = __half22float2(*reinterpret_cast<const __half2*>(&kk.x));
            const float2 k1 = __half22float2(*reinterpret_cast<const __half2*>(&kk.y));
            const float2 k2 = __half22float2(*reinterpret_cast<const __half2*>(&kk.z));
            const float2 k3 = __half22float2(*reinterpret_cast<const __half2*>(&kk.w));
            a[x] = k0.x * qv[x][0].x + k0.y * qv[x][0].y +
                   k1.x * qv[x][0].z + k1.y * qv[x][0].w +
                   k2.x * qv[x][1].x + k2.y * qv[x][1].y +
                   k3.x * qv[x][1].z + k3.y * qv[x][1].w;
        }
#pragma unroll
        for (int x = 0; x < 2; x++) {
            a[x] += __shfl_xor_sync(0xffffffffu, a[x], 1);
            a[x] += __shfl_xor_sync(0xffffffffu, a[x], 2);
            a[x] += __shfl_xor_sync(0xffffffffu, a[x], 4);
        }
        if ((lane & 7) == 0 && j < n) {
            const int g = lane >> 3;
#pragma unroll
            for (int x = 0; x < 2; x++)
                sc_s[g + 4 * x][j] = a[x];
        }
    }
    __syncthreads();

    // ---- Softmax over <=64 scores, 2 per lane (warp h owns row h).
    const float s0 = sc_s[h][lane];
    const float s1 = sc_s[h][lane + 32];
    float m = fmaxf(s0, s1);
#pragma unroll
    for (int o = 16; o >= 1; o >>= 1) m = fmaxf(m, __shfl_xor_sync(0xffffffffu, m, o));

    const float e0 = __expf(s0 - m);   // exp(-inf) -> 0 for padded slots
    const float e1 = __expf(s1 - m);
    float sum = e0 + e1;
#pragma unroll
    for (int o = 16; o >= 1; o >>= 1) sum += __shfl_xor_sync(0xffffffffu, sum, o);

    const float inv = __fdividef(1.0f, sum);
    // publish packed (col, prob) pairs; padded slots get prob == 0 exactly
    {
        float2 pr;
        pr.x = __int_as_float(cols_s[lane]);
        pr.y = e0 * inv;
        pp_s[h][lane] = pr;
        if (lane < NCPAD - 32) {
            float2 pr2;
            pr2.x = __int_as_float(cols_s[lane + 32]);
            pr2.y = e1 * inv;
            pp_s[h][lane + 32] = pr2;
        }
    }
    __syncwarp();

    // ---- Phase 2: out = sum_j p_j * V16[col_j][h]. 2 pairs per LDS.128,
    //      static fully-unrolled loop, two accumulator chains.
    const __half* vb = gV16 + ((size_t)b * LSEQ * NH + h) * NE;
    float ax = 0.f, ay = 0.f, bx = 0.f, by = 0.f;
    const float4* pp4 = reinterpret_cast<const float4*>(pp_s[h]);
#pragma unroll
    for (int j2 = 0; j2 < NCPAD / 2; j2++) {
        const float4 cp = pp4[j2];          // (col0, p0, col1, p1)
        const int c0 = __float_as_int(cp.x);
        const int c1 = __float_as_int(cp.z);
        const __half2 v0 = reinterpret_cast<const __half2*>(
            vb + (size_t)c0 * (NH * NE))[lane];
        const __half2 v1 = reinterpret_cast<const __half2*>(
            vb + (size_t)c1 * (NH * NE))[lane];
        const float2 f0 = __half22float2(v0);
        const float2 f1 = __half22float2(v1);
        ax += cp.y * f0.x;
        ay += cp.y * f0.y;
        bx += cp.w * f1.x;
        by += cp.w * f1.y;
    }

    float2 o2; o2.x = ax + bx; o2.y = ay + by;
    reinterpret_cast<float2*>(out + ((size_t)(b * LSEQ + i) * NH + h) * NE)[lane] = o2;
}

extern "C" void kernel_launch(void* const* d_in, const int* in_sizes, int n_in,
                              void* d_out, int out_size) {
    const float* q = (const float*)d_in[0];  // [B,L,H,E] f32
    const float* k = (const float*)d_in[1];  // [B,L,H,E] f32
    const float* v = (const float*)d_in[2];  // [B,L,H,D] f32

    prep<<<NCVT + 8, 256>>>(k, v);
    dim3 grid(LSEQ, NB);
    attn<<<grid, 256>>>(q, (float*)d_out);
}